// round 9
// baseline (speedup 1.0000x reference)
#include <cuda_runtime.h>
#include <cstdint>

#define TILE_E   96
#define NTHREADS 768

// smem layout in 4-byte words
#define W1F    0        // 32768 : W1 fragment-major tf32
#define XA_F   32768    // 12288 : X half A (96 x 128, 16B-swizzled, tf32 after convert pass)
#define XB_F   45056    // 12288 : X half B
#define SIDX_F 57344    // 192 ints (96 src, 96 dst)
#define PART_F 57536    // 384 floats
#define SMEM_W 57920    // * 4 = 231680 B

__device__ __align__(16) unsigned g_w2frag[128 * 64];   // W2 fragment-major tf32, L2-resident

__device__ __forceinline__ uint32_t f2tf(float f) {
    uint32_t r; asm("cvt.rna.tf32.f32 %0, %1;" : "=r"(r) : "f"(f)); return r;
}
__device__ __forceinline__ uint32_t smem_u32(const void* p) {
    uint32_t a; asm("{ .reg .u64 t; cvta.to.shared.u64 t, %1; cvt.u32.u64 %0, t; }" : "=r"(a) : "l"(p));
    return a;
}
__device__ __forceinline__ void mma_tf32(float c[4],
    uint32_t a0, uint32_t a1, uint32_t a2, uint32_t a3, uint32_t b0, uint32_t b1)
{
    asm volatile("mma.sync.aligned.m16n8k8.row.col.f32.tf32.tf32.f32 "
        "{%0,%1,%2,%3}, {%4,%5,%6,%7}, {%8,%9}, {%0,%1,%2,%3};"
        : "+f"(c[0]), "+f"(c[1]), "+f"(c[2]), "+f"(c[3])
        : "r"(a0), "r"(a1), "r"(a2), "r"(a3), "r"(b0), "r"(b1));
}
__device__ __forceinline__ void cpa16(uint32_t s, const void* g) {
    asm volatile("cp.async.cg.shared.global [%0], [%1], 16;" :: "r"(s), "l"(g));
}
#define CPA_COMMIT() asm volatile("cp.async.commit_group;" ::: "memory")
#define CPA_WAIT(n)  asm volatile("cp.async.wait_group %0;" :: "n"(n) : "memory")

__global__ void repack_w2(const float* __restrict__ W2) {
    int i = blockIdx.x * blockDim.x + threadIdx.x;   // i over W2[k][m]
    if (i < 128 * 64) {
        int k = i >> 6, m = i & 63;
        int kk = k >> 3, ktg = k & 3, t = (k >> 2) & 1;
        int nqq = m >> 4, ng = m & 7, ntl = (m >> 3) & 1;
        int flat = (((kk * 4 + nqq) * 32) + ng * 4 + ktg) * 4 + ntl * 2 + t;
        g_w2frag[flat] = f2tf(__ldg(W2 + i));
    }
}

// convert the 16 floats this thread staged (in place, f32 -> tf32 bits)
__device__ __forceinline__ void cvt_self(uint32_t* xh, int ge, int gq, int gsw) {
    #pragma unroll
    for (int j = 0; j < 4; j++) {
        uint32_t* p = xh + ge * 128 + ((gq * 16 + j * 4) ^ gsw);
        uint4 v = *reinterpret_cast<uint4*>(p);
        v.x = f2tf(__uint_as_float(v.x)); v.y = f2tf(__uint_as_float(v.y));
        v.z = f2tf(__uint_as_float(v.z)); v.w = f2tf(__uint_as_float(v.w));
        *reinterpret_cast<uint4*>(p) = v;
    }
}

// 16 k-step MMA segment over a 96x128 staged half (operands already tf32 bits)
__device__ __forceinline__ void mma_seg(const uint32_t* __restrict__ xm,
                                        const uint32_t* __restrict__ w1f,
                                        int kkbase, int nq, int lane, int g, int tg,
                                        float acc[4][4])
{
    const int asw = g << 2;
    #pragma unroll 8
    for (int kk2 = 0; kk2 < 16; kk2++) {
        const int kk = kkbase + kk2;
        const int k0 = kk2 * 8;
        uint32_t a0 = xm[g * 128 + ((k0 + tg) ^ asw)];
        uint32_t a1 = xm[(g + 8) * 128 + ((k0 + tg) ^ asw)];
        uint32_t a2 = xm[g * 128 + ((k0 + tg + 4) ^ asw)];
        uint32_t a3 = xm[(g + 8) * 128 + ((k0 + tg + 4) ^ asw)];
        const uint4 bfA = *reinterpret_cast<const uint4*>(
            w1f + ((((kk * 4 + nq) * 2 + 0) * 32) + lane) * 4);
        const uint4 bfB = *reinterpret_cast<const uint4*>(
            w1f + ((((kk * 4 + nq) * 2 + 1) * 32) + lane) * 4);
        mma_tf32(acc[0], a0, a1, a2, a3, bfA.x, bfA.y);
        mma_tf32(acc[1], a0, a1, a2, a3, bfA.z, bfA.w);
        mma_tf32(acc[2], a0, a1, a2, a3, bfB.x, bfB.y);
        mma_tf32(acc[3], a0, a1, a2, a3, bfB.z, bfB.w);
    }
}

extern __shared__ float smem[];

__global__ void __launch_bounds__(NTHREADS, 1) lp_tc(
    const float* __restrict__ z,
    const int*   __restrict__ ei,
    const float* __restrict__ W1,
    const float* __restrict__ b1,
    const float* __restrict__ b2,
    const float* __restrict__ W3,
    const float* __restrict__ b3,
    float* __restrict__ out,
    int E, int n_nodes, int ntiles)
{
    const int tid  = threadIdx.x;
    const int lane = tid & 31;
    const int wid  = tid >> 5;
    const int tg   = lane & 3;
    const int g    = lane >> 2;
    uint32_t* s32 = reinterpret_cast<uint32_t*>(smem);
    int* sidx = reinterpret_cast<int*>(smem + SIDX_F);
    float* part = smem + PART_F;
    const uint32_t smb = smem_u32(smem);

    // ---- one-time: W1 -> smem fragment-major ----
    for (int i = tid; i < 256 * 128; i += NTHREADS) {
        int k = i >> 7, n = i & 127;
        int kk = k >> 3, ktg = k & 3, t = (k >> 2) & 1;
        int nqq = n >> 5, ng = n & 7, ntl = (n >> 3) & 3;
        int flat = ((((kk * 4 + nqq) * 2 + (ntl >> 1)) * 32) + ng * 4 + ktg) * 4 + (ntl & 1) * 2 + t;
        s32[W1F + flat] = f2tf(__ldg(W1 + i));
    }

    const int mtile = wid >> 2;
    const int nq    = wid & 3;
    const int nb1 = nq * 32;
    const int nb2 = nq * 16;

    float b1f[4][2], b2f[2][2], w3f[2][2];
    #pragma unroll
    for (int nt = 0; nt < 4; nt++) {
        b1f[nt][0] = __ldg(b1 + nb1 + nt * 8 + 2 * tg);
        b1f[nt][1] = __ldg(b1 + nb1 + nt * 8 + 2 * tg + 1);
    }
    #pragma unroll
    for (int nt = 0; nt < 2; nt++) {
        b2f[nt][0] = __ldg(b2 + nb2 + nt * 8 + 2 * tg);
        b2f[nt][1] = __ldg(b2 + nb2 + nt * 8 + 2 * tg + 1);
        w3f[nt][0] = __ldg(W3 + nb2 + nt * 8 + 2 * tg);
        w3f[nt][1] = __ldg(W3 + nb2 + nt * 8 + 2 * tg + 1);
    }
    const float b3v = __ldg(b3);

    const int ge  = tid >> 3;          // gather: edge 0..95
    const int gq  = tid & 7;           // 16-float quarter
    const int gsw = (ge & 7) << 2;

    uint32_t xa_s = smb + XA_F * 4, xb_s = smb + XB_F * 4;
    uint32_t *xa = s32 + XA_F, *xb = s32 + XB_F;

    // ---- prologue: idx(t0) + src-half(t0) -> XA ----
    {
        if (tid < 192) {
            long long eid = (long long)blockIdx.x * TILE_E + (tid < 96 ? tid : tid - 96);
            if (eid >= (long long)E) eid = (long long)E - 1;
            int v = __ldg(ei + (tid < 96 ? eid : (long long)E + eid));
            sidx[tid] = min(max(v, 0), n_nodes - 1);
        }
        __syncthreads();
        const float* gp = z + (size_t)sidx[ge] * 128 + gq * 16;
        #pragma unroll
        for (int j = 0; j < 4; j++)
            cpa16(xa_s + (ge * 128 + ((gq * 16 + j * 4) ^ gsw)) * 4, gp + j * 4);
        CPA_COMMIT();
    }

    for (int tile = blockIdx.x; tile < ntiles; tile += gridDim.x) {
        const long long e0 = (long long)tile * TILE_E;
        const int tn = tile + gridDim.x;
        const bool hn = tn < ntiles;

        int nv = 0;
        if (hn && tid < 192) {
            long long eid = (long long)tn * TILE_E + (tid < 96 ? tid : tid - 96);
            if (eid >= (long long)E) eid = (long long)E - 1;
            nv = __ldg(ei + (tid < 96 ? eid : (long long)E + eid));
            nv = min(max(nv, 0), n_nodes - 1);
        }

        // issue dst-half(t) -> XB
        {
            const float* gp = z + (size_t)sidx[96 + ge] * 128 + gq * 16;
            #pragma unroll
            for (int j = 0; j < 4; j++)
                cpa16(xb_s + (ge * 128 + ((gq * 16 + j * 4) ^ gsw)) * 4, gp + j * 4);
        }
        CPA_COMMIT();

        CPA_WAIT(1);                       // src half landed
        cvt_self(xa, ge, gq, gsw);         // f32 -> tf32 in place (own bytes)
        __syncthreads();

        // ---- layer 1, K 0..127 ----
        float acc[4][4];
        #pragma unroll
        for (int nt = 0; nt < 4; nt++)
            #pragma unroll
            for (int q = 0; q < 4; q++) acc[nt][q] = 0.f;
        mma_seg(xa + (mtile * 16) * 128, s32 + W1F, 0, nq, lane, g, tg, acc);

        CPA_WAIT(0);                       // dst half landed
        cvt_self(xb, ge, gq, gsw);
        __syncthreads();

        // ---- layer 1, K 128..255 ----
        mma_seg(xb + (mtile * 16) * 128, s32 + W1F, 16, nq, lane, g, tg, acc);

        if (hn && tid < 192) sidx[tid] = nv;
        __syncthreads();                   // K2 reads done; sidx(t+1) visible

        // issue src-half(t+1) -> XB (overlaps epilogue + layer 2/3)
        if (hn) {
            const float* gp = z + (size_t)sidx[ge] * 128 + gq * 16;
            #pragma unroll
            for (int j = 0; j < 4; j++)
                cpa16(xb_s + (ge * 128 + ((gq * 16 + j * 4) ^ gsw)) * 4, gp + j * 4);
        }
        CPA_COMMIT();

        // ---- h1 = tf32(relu(acc + b1)) -> XA (stored converted) ----
        {
            const int rw1 = (mtile * 16 + g) * 128;
            const int rw2 = (mtile * 16 + g + 8) * 128;
            #pragma unroll
            for (int nt = 0; nt < 4; nt++) {
                const int j = (nb1 + nt * 8 + 2 * tg) ^ (g << 2);
                uint2 lo, hi;
                lo.x = f2tf(fmaxf(acc[nt][0] + b1f[nt][0], 0.f));
                lo.y = f2tf(fmaxf(acc[nt][1] + b1f[nt][1], 0.f));
                hi.x = f2tf(fmaxf(acc[nt][2] + b1f[nt][0], 0.f));
                hi.y = f2tf(fmaxf(acc[nt][3] + b1f[nt][1], 0.f));
                *reinterpret_cast<uint2*>(xa + rw1 + j) = lo;
                *reinterpret_cast<uint2*>(xa + rw2 + j) = hi;
            }
        }
        __syncthreads();

        // ---- layer 2: C[16 x 16] = H1 @ W2, K=128 ----
        float acc2[2][4];
        #pragma unroll
        for (int nt = 0; nt < 2; nt++)
            #pragma unroll
            for (int q = 0; q < 4; q++) acc2[nt][q] = 0.f;
        {
            const uint32_t* xm = xa + (mtile * 16) * 128;
            const int asw = g << 2;
            #pragma unroll 8
            for (int kk = 0; kk < 16; kk++) {
                const int k0 = kk * 8;
                uint32_t a0 = xm[g * 128 + ((k0 + tg) ^ asw)];
                uint32_t a1 = xm[(g + 8) * 128 + ((k0 + tg) ^ asw)];
                uint32_t a2 = xm[g * 128 + ((k0 + tg + 4) ^ asw)];
                uint32_t a3 = xm[(g + 8) * 128 + ((k0 + tg + 4) ^ asw)];
                const uint4 bf = __ldg(reinterpret_cast<const uint4*>(
                    g_w2frag + (((kk * 4 + nq) * 32) + lane) * 4));
                mma_tf32(acc2[0], a0, a1, a2, a3, bf.x, bf.y);
                mma_tf32(acc2[1], a0, a1, a2, a3, bf.z, bf.w);
            }
        }

        // ---- layer 3 ----
        float p0 = 0.f, p1 = 0.f;
        #pragma unroll
        for (int nt = 0; nt < 2; nt++) {
            p0 += fmaxf(acc2[nt][0] + b2f[nt][0], 0.f) * w3f[nt][0]
                + fmaxf(acc2[nt][1] + b2f[nt][1], 0.f) * w3f[nt][1];
            p1 += fmaxf(acc2[nt][2] + b2f[nt][0], 0.f) * w3f[nt][0]
                + fmaxf(acc2[nt][3] + b2f[nt][1], 0.f) * w3f[nt][1];
        }
        p0 += __shfl_xor_sync(0xffffffffu, p0, 1);
        p0 += __shfl_xor_sync(0xffffffffu, p0, 2);
        p1 += __shfl_xor_sync(0xffffffffu, p1, 1);
        p1 += __shfl_xor_sync(0xffffffffu, p1, 2);
        if (tg == 0) {
            part[(mtile * 16 + g) * 4 + nq]     = p0;
            part[(mtile * 16 + g + 8) * 4 + nq] = p1;
        }
        __syncthreads();

        if (tid < TILE_E) {
            long long eid = e0 + tid;
            if (eid < (long long)E)
                out[eid] = part[tid * 4] + part[tid * 4 + 1]
                         + part[tid * 4 + 2] + part[tid * 4 + 3] + b3v;
        }

        { uint32_t* tp = xa; xa = xb; xb = tp; uint32_t ts = xa_s; xa_s = xb_s; xb_s = ts; }
    }
}

extern "C" void kernel_launch(void* const* d_in, const int* in_sizes, int n_in,
                              void* d_out, int out_size)
{
    const float* z  = (const float*)d_in[0];
    const int*   ei = (const int*)d_in[1];
    const float* W1 = (const float*)d_in[2];
    const float* b1 = (const float*)d_in[3];
    const float* W2 = (const float*)d_in[4];
    const float* b2 = (const float*)d_in[5];
    const float* W3 = (const float*)d_in[6];
    const float* b3 = (const float*)d_in[7];
    float* out = (float*)d_out;

    const int E       = in_sizes[1] / 2;
    const int n_nodes = in_sizes[0] / 128;
    const int ntiles  = (E + TILE_E - 1) / TILE_E;
    const int smem_bytes = SMEM_W * 4;

    static bool attr_set = false;
    if (!attr_set) {
        cudaFuncSetAttribute(lp_tc, cudaFuncAttributeMaxDynamicSharedMemorySize, smem_bytes);
        attr_set = true;
    }

    repack_w2<<<16, 512>>>(W2);

    int grid = 148;
    if (grid > ntiles) grid = ntiles;
    lp_tc<<<grid, NTHREADS, smem_bytes>>>(z, ei, W1, b1, b2, W3, b3, out, E, n_nodes, ntiles);
}

// round 10
// speedup vs baseline: 1.4838x; 1.4838x over previous
#include <cuda_runtime.h>
#include <cstdint>

#define TILE_E   160
#define NTHREADS 640

// smem layout in 4-byte words
#define W1F    0        // 32768 : W1 fragment-major tf32
#define X_F    32768    // 20480 : X stages / h1 (XA = first 10240, XB = next 10240)
#define PART_F 53248    // 640 floats
#define SMEM_W 53888    // * 4 = 215552 B

__device__ __align__(16) unsigned g_w2frag[128 * 64];   // W2 fragment-major tf32, L2-resident

__device__ __forceinline__ uint32_t f2tf(float f) {
    uint32_t r; asm("cvt.rna.tf32.f32 %0, %1;" : "=r"(r) : "f"(f)); return r;
}
__device__ __forceinline__ uint32_t smem_u32(const void* p) {
    uint32_t a; asm("{ .reg .u64 t; cvta.to.shared.u64 t, %1; cvt.u32.u64 %0, t; }" : "=r"(a) : "l"(p));
    return a;
}
__device__ __forceinline__ void mma_tf32(float c[4],
    uint32_t a0, uint32_t a1, uint32_t a2, uint32_t a3, uint32_t b0, uint32_t b1)
{
    asm volatile("mma.sync.aligned.m16n8k8.row.col.f32.tf32.tf32.f32 "
        "{%0,%1,%2,%3}, {%4,%5,%6,%7}, {%8,%9}, {%0,%1,%2,%3};"
        : "+f"(c[0]), "+f"(c[1]), "+f"(c[2]), "+f"(c[3])
        : "r"(a0), "r"(a1), "r"(a2), "r"(a3), "r"(b0), "r"(b1));
}
__device__ __forceinline__ void cpa16(uint32_t s, const void* g) {
    asm volatile("cp.async.cg.shared.global [%0], [%1], 16;" :: "r"(s), "l"(g));
}
#define CPA_COMMIT() asm volatile("cp.async.commit_group;" ::: "memory")
#define CPA_WAIT(n)  asm volatile("cp.async.wait_group %0;" :: "n"(n) : "memory")

__global__ void repack_w2(const float* __restrict__ W2) {
    int i = blockIdx.x * blockDim.x + threadIdx.x;   // i over W2[k][m]
    if (i < 128 * 64) {
        int k = i >> 6, m = i & 63;
        int kk = k >> 3, ktg = k & 3, t = (k >> 2) & 1;
        int nqq = m >> 4, ng = m & 7, ntl = (m >> 3) & 1;
        int flat = (((kk * 4 + nqq) * 32) + ng * 4 + ktg) * 4 + ntl * 2 + t;
        g_w2frag[flat] = f2tf(__ldg(W2 + i));
    }
}

extern __shared__ float smem[];

// 8 k-step MMA over one 160x64 stage (row stride 64 words); A converted inline.
__device__ __forceinline__ void mma_stage(const uint32_t* __restrict__ xs,
                                          const uint32_t* __restrict__ w1f,
                                          int kkbase, int base, int nq,
                                          int lane, int g, int tg,
                                          float acc[2][4][4])
{
    const int asw = g << 2;
    #pragma unroll
    for (int kk2 = 0; kk2 < 8; kk2++) {
        const int kk = kkbase + kk2;
        const int k0 = kk2 * 8;
        const int c0 = (k0 + tg) ^ asw;
        const int c1 = (k0 + tg + 4) ^ asw;
        uint32_t a[2][4];
        #pragma unroll
        for (int mt = 0; mt < 2; mt++) {
            const int r1 = (base + mt * 16 + g) * 64;
            const int r2 = (base + mt * 16 + g + 8) * 64;
            a[mt][0] = f2tf(__uint_as_float(xs[r1 + c0]));
            a[mt][1] = f2tf(__uint_as_float(xs[r2 + c0]));
            a[mt][2] = f2tf(__uint_as_float(xs[r1 + c1]));
            a[mt][3] = f2tf(__uint_as_float(xs[r2 + c1]));
        }
        const uint4 bfA = *reinterpret_cast<const uint4*>(
            w1f + ((((kk * 4 + nq) * 2 + 0) * 32) + lane) * 4);
        const uint4 bfB = *reinterpret_cast<const uint4*>(
            w1f + ((((kk * 4 + nq) * 2 + 1) * 32) + lane) * 4);
        #pragma unroll
        for (int mt = 0; mt < 2; mt++) {
            mma_tf32(acc[mt][0], a[mt][0], a[mt][1], a[mt][2], a[mt][3], bfA.x, bfA.y);
            mma_tf32(acc[mt][1], a[mt][0], a[mt][1], a[mt][2], a[mt][3], bfA.z, bfA.w);
            mma_tf32(acc[mt][2], a[mt][0], a[mt][1], a[mt][2], a[mt][3], bfB.x, bfB.y);
            mma_tf32(acc[mt][3], a[mt][0], a[mt][1], a[mt][2], a[mt][3], bfB.z, bfB.w);
        }
    }
}

__global__ void __launch_bounds__(NTHREADS, 1) lp_tc(
    const float* __restrict__ z,
    const int*   __restrict__ ei,
    const float* __restrict__ W1,
    const float* __restrict__ b1,
    const float* __restrict__ b2,
    const float* __restrict__ W3,
    const float* __restrict__ b3,
    float* __restrict__ out,
    int E, int n_nodes, int ntiles)
{
    const int tid  = threadIdx.x;
    const int lane = tid & 31;
    const int wid  = tid >> 5;
    const int tg   = lane & 3;
    const int g    = lane >> 2;
    uint32_t* s32 = reinterpret_cast<uint32_t*>(smem);
    float* part = smem + PART_F;
    const uint32_t smb = smem_u32(smem);

    // ---- one-time: W1 -> smem fragment-major (validated layout) ----
    for (int i = tid; i < 256 * 128; i += NTHREADS) {
        int k = i >> 7, n = i & 127;
        int kk = k >> 3, ktg = k & 3, t = (k >> 2) & 1;
        int nqq = n >> 5, ng = n & 7, ntl = (n >> 3) & 3;
        int flat = ((((kk * 4 + nqq) * 2 + (ntl >> 1)) * 32) + ng * 4 + ktg) * 4 + (ntl & 1) * 2 + t;
        s32[W1F + flat] = f2tf(__ldg(W1 + i));
    }

    // warp roles: 20 warps = 5 M-groups (32 edges) x 4 N-quarters
    const int wm  = wid >> 2;
    const int nq  = wid & 3;
    const int base = wm * 32;
    const int nb1 = nq * 32;
    const int nb2 = nq * 16;

    float b1f[4][2], b2f[2][2], w3f[2][2];
    #pragma unroll
    for (int nt = 0; nt < 4; nt++) {
        b1f[nt][0] = __ldg(b1 + nb1 + nt * 8 + 2 * tg);
        b1f[nt][1] = __ldg(b1 + nb1 + nt * 8 + 2 * tg + 1);
    }
    #pragma unroll
    for (int nt = 0; nt < 2; nt++) {
        b2f[nt][0] = __ldg(b2 + nb2 + nt * 8 + 2 * tg);
        b2f[nt][1] = __ldg(b2 + nb2 + nt * 8 + 2 * tg + 1);
        w3f[nt][0] = __ldg(W3 + nb2 + nt * 8 + 2 * tg);
        w3f[nt][1] = __ldg(W3 + nb2 + nt * 8 + 2 * tg + 1);
    }
    const float b3v = __ldg(b3);

    // gather role: 4 threads per edge, each stages 16 floats of a 64-col stage slice
    const int ge  = tid >> 2;           // edge 0..159
    const int gq  = tid & 3;            // quarter of 64 cols
    const int gsw = (ge & 7) << 2;

    const uint32_t xa_s = smb + X_F * 4;                 // stage A (10240 words)
    const uint32_t xb_s = smb + (X_F + 10240) * 4;       // stage B
    const uint32_t* xa = s32 + X_F;
    const uint32_t* xb = s32 + X_F + 10240;
    uint32_t* xh = s32 + X_F;                            // h1 region (160 x 128)

    // edge indices for this thread's gather edge
    int csrc = 0, cdst = 0;
    {
        long long eid = (long long)blockIdx.x * TILE_E + ge;
        if (eid >= (long long)E) eid = (long long)E - 1;
        csrc = min(max(__ldg(ei + eid), 0), n_nodes - 1);
        cdst = min(max(__ldg(ei + (long long)E + eid), 0), n_nodes - 1);
    }
    __syncthreads();   // W1 repack done before first MMA (stage issues are async)

    // helper lambda: issue one stage (s: 0=src-lo,1=src-hi,2=dst-lo,3=dst-hi)
    auto issue = [&](int s, uint32_t buf_s, int src, int dst) {
        const int node = (s < 2) ? src : dst;
        const float* gp = z + (size_t)node * 128 + (s & 1) * 64 + gq * 16;
        #pragma unroll
        for (int j = 0; j < 4; j++)
            cpa16(buf_s + (ge * 64 + ((gq * 16 + j * 4) ^ gsw)) * 4, gp + j * 4);
    };

    // prologue: stage 0 of first tile
    issue(0, xa_s, csrc, cdst);
    CPA_COMMIT();

    for (int tile = blockIdx.x; tile < ntiles; tile += gridDim.x) {
        const long long e0 = (long long)tile * TILE_E;
        const int tn = tile + gridDim.x;
        const bool hn = tn < ntiles;

        float acc[2][4][4];
        #pragma unroll
        for (int mt = 0; mt < 2; mt++)
            #pragma unroll
            for (int nt = 0; nt < 4; nt++)
                #pragma unroll
                for (int q = 0; q < 4; q++) acc[mt][nt][q] = 0.f;

        issue(1, xb_s, csrc, cdst); CPA_COMMIT();
        CPA_WAIT(1); __syncthreads();                       // s0 ready
        mma_stage(xa, s32 + W1F, 0, base, nq, lane, g, tg, acc);
        __syncthreads();                                    // XA consumed

        issue(2, xa_s, csrc, cdst); CPA_COMMIT();
        CPA_WAIT(1); __syncthreads();                       // s1 ready
        mma_stage(xb, s32 + W1F, 8, base, nq, lane, g, tg, acc);
        __syncthreads();                                    // XB consumed

        issue(3, xb_s, csrc, cdst); CPA_COMMIT();
        CPA_WAIT(1); __syncthreads();                       // s2 ready
        mma_stage(xa, s32 + W1F, 16, base, nq, lane, g, tg, acc);
        CPA_WAIT(0); __syncthreads();                       // s3 ready, XA reads done
        mma_stage(xb, s32 + W1F, 24, base, nq, lane, g, tg, acc);
        __syncthreads();                                    // all layer-1 reads done

        // ---- h1 = tf32(relu(acc + b1)) -> xh (row stride 128, stored converted) ----
        #pragma unroll
        for (int mt = 0; mt < 2; mt++) {
            const int rw1 = (base + mt * 16 + g) * 128;
            const int rw2 = (base + mt * 16 + g + 8) * 128;
            #pragma unroll
            for (int nt = 0; nt < 4; nt++) {
                const int j = (nb1 + nt * 8 + 2 * tg) ^ (g << 2);
                uint2 lo, hi;
                lo.x = f2tf(fmaxf(acc[mt][nt][0] + b1f[nt][0], 0.f));
                lo.y = f2tf(fmaxf(acc[mt][nt][1] + b1f[nt][1], 0.f));
                hi.x = f2tf(fmaxf(acc[mt][nt][2] + b1f[nt][0], 0.f));
                hi.y = f2tf(fmaxf(acc[mt][nt][3] + b1f[nt][1], 0.f));
                *reinterpret_cast<uint2*>(xh + rw1 + j) = lo;
                *reinterpret_cast<uint2*>(xh + rw2 + j) = hi;
            }
        }
        __syncthreads();

        // ---- layer 2: C[32 x 16] = H1 @ W2, K=128 (A already tf32 bits) ----
        float acc2[2][2][4];
        #pragma unroll
        for (int mt = 0; mt < 2; mt++)
            #pragma unroll
            for (int nt = 0; nt < 2; nt++)
                #pragma unroll
                for (int q = 0; q < 4; q++) acc2[mt][nt][q] = 0.f;
        {
            const int asw = g << 2;
            #pragma unroll 4
            for (int kk = 0; kk < 16; kk++) {
                const int k0 = kk * 8;
                const int c0 = (k0 + tg) ^ asw;
                const int c1 = (k0 + tg + 4) ^ asw;
                uint32_t a[2][4];
                #pragma unroll
                for (int mt = 0; mt < 2; mt++) {
                    const int r1 = (base + mt * 16 + g) * 128;
                    const int r2 = (base + mt * 16 + g + 8) * 128;
                    a[mt][0] = xh[r1 + c0];
                    a[mt][1] = xh[r2 + c0];
                    a[mt][2] = xh[r1 + c1];
                    a[mt][3] = xh[r2 + c1];
                }
                const uint4 bf = __ldg(reinterpret_cast<const uint4*>(
                    g_w2frag + (((kk * 4 + nq) * 32) + lane) * 4));
                #pragma unroll
                for (int mt = 0; mt < 2; mt++) {
                    mma_tf32(acc2[mt][0], a[mt][0], a[mt][1], a[mt][2], a[mt][3], bf.x, bf.y);
                    mma_tf32(acc2[mt][1], a[mt][0], a[mt][1], a[mt][2], a[mt][3], bf.z, bf.w);
                }
            }
        }
        __syncthreads();   // h1 reads done before next tile's s0 overwrites XA

        // ---- prefetch next tile: indices + stage 0 -> XA (overlaps epilogue) ----
        if (hn) {
            long long eid = (long long)tn * TILE_E + ge;
            if (eid >= (long long)E) eid = (long long)E - 1;
            csrc = min(max(__ldg(ei + eid), 0), n_nodes - 1);
            cdst = min(max(__ldg(ei + (long long)E + eid), 0), n_nodes - 1);
            issue(0, xa_s, csrc, cdst);
        }
        CPA_COMMIT();

        // ---- layer 3: dot with W3, shfl reduce over tg, combine via part ----
        #pragma unroll
        for (int mt = 0; mt < 2; mt++) {
            float p0 = 0.f, p1 = 0.f;
            #pragma unroll
            for (int nt = 0; nt < 2; nt++) {
                p0 += fmaxf(acc2[mt][nt][0] + b2f[nt][0], 0.f) * w3f[nt][0]
                    + fmaxf(acc2[mt][nt][1] + b2f[nt][1], 0.f) * w3f[nt][1];
                p1 += fmaxf(acc2[mt][nt][2] + b2f[nt][0], 0.f) * w3f[nt][0]
                    + fmaxf(acc2[mt][nt][3] + b2f[nt][1], 0.f) * w3f[nt][1];
            }
            p0 += __shfl_xor_sync(0xffffffffu, p0, 1);
            p0 += __shfl_xor_sync(0xffffffffu, p0, 2);
            p1 += __shfl_xor_sync(0xffffffffu, p1, 1);
            p1 += __shfl_xor_sync(0xffffffffu, p1, 2);
            if (tg == 0) {
                part[(base + mt * 16 + g) * 4 + nq]     = p0;
                part[(base + mt * 16 + g + 8) * 4 + nq] = p1;
            }
        }
        __syncthreads();

        if (tid < TILE_E) {
            long long eid = e0 + tid;
            if (eid < (long long)E)
                out[eid] = part[tid * 4] + part[tid * 4 + 1]
                         + part[tid * 4 + 2] + part[tid * 4 + 3] + b3v;
        }
        // no further sync needed: next loop's first touch of part is preceded by many barriers
    }
}

extern "C" void kernel_launch(void* const* d_in, const int* in_sizes, int n_in,
                              void* d_out, int out_size)
{
    const float* z  = (const float*)d_in[0];
    const int*   ei = (const int*)d_in[1];
    const float* W1 = (const float*)d_in[2];
    const float* b1 = (const float*)d_in[3];
    const float* W2 = (const float*)d_in[4];
    const float* b2 = (const float*)d_in[5];
    const float* W3 = (const float*)d_in[6];
    const float* b3 = (const float*)d_in[7];
    float* out = (float*)d_out;

    const int E       = in_sizes[1] / 2;
    const int n_nodes = in_sizes[0] / 128;
    const int ntiles  = (E + TILE_E - 1) / TILE_E;
    const int smem_bytes = SMEM_W * 4;   // 215552 B

    static bool attr_set = false;
    if (!attr_set) {
        cudaFuncSetAttribute(lp_tc, cudaFuncAttributeMaxDynamicSharedMemorySize, smem_bytes);
        attr_set = true;
    }

    repack_w2<<<16, 512>>>(W2);

    int grid = 148;
    if (grid > ntiles) grid = ntiles;
    lp_tc<<<grid, NTHREADS, smem_bytes>>>(z, ei, W1, b1, b2, W3, b3, out, E, n_nodes, ntiles);
}

// round 11
// speedup vs baseline: 2.1413x; 1.4431x over previous
#include <cuda_runtime.h>
#include <cuda_fp16.h>
#include <cstdint>

#define TILE_E   160
#define NTHREADS 640

// smem layout in 4-byte words
#define W1F    0        // 16384 : W1 fragment-major fp16 (64 KB)
#define XA_F   16384    // 10240 : f32 stage A (160 x 64)
#define XB_F   26624    // 10240 : f32 stage B
#define XH_F   36864    // 20480 : fp16 X (160 rows x 128 half2 words); h1 reuses rows w/ stride 64
#define PART_F 57344    // 640 floats
#define SMEM_W 57984    // * 4 = 231936 B

__device__ __align__(16) __half g_w2h[128 * 64];   // W2 fragment-major fp16, L2-resident

__device__ __forceinline__ uint32_t smem_u32(const void* p) {
    uint32_t a; asm("{ .reg .u64 t; cvta.to.shared.u64 t, %1; cvt.u32.u64 %0, t; }" : "=r"(a) : "l"(p));
    return a;
}
__device__ __forceinline__ void mma_f16(float c[4],
    uint32_t a0, uint32_t a1, uint32_t a2, uint32_t a3, uint32_t b0, uint32_t b1)
{
    asm volatile("mma.sync.aligned.m16n8k16.row.col.f32.f16.f16.f32 "
        "{%0,%1,%2,%3}, {%4,%5,%6,%7}, {%8,%9}, {%0,%1,%2,%3};"
        : "+f"(c[0]), "+f"(c[1]), "+f"(c[2]), "+f"(c[3])
        : "r"(a0), "r"(a1), "r"(a2), "r"(a3), "r"(b0), "r"(b1));
}
__device__ __forceinline__ void cpa16(uint32_t s, const void* g) {
    asm volatile("cp.async.cg.shared.global [%0], [%1], 16;" :: "r"(s), "l"(g));
}
#define CPA_COMMIT() asm volatile("cp.async.commit_group;" ::: "memory")
#define CPA_WAIT(n)  asm volatile("cp.async.wait_group %0;" :: "n"(n) : "memory")

__device__ __forceinline__ uint32_t packh2(float lo, float hi) {
    __half2 h = __floats2half2_rn(lo, hi);
    return *reinterpret_cast<uint32_t*>(&h);
}

__global__ void repack_w2(const float* __restrict__ W2) {
    int i = blockIdx.x * blockDim.x + threadIdx.x;   // i over W2[k][m], k<128, m<64
    if (i < 128 * 64) {
        int k = i >> 6, m = i & 63;
        int kk = k >> 4, klo = k & 15, half = klo >> 3, tgk = (klo >> 1) & 3, h = klo & 1;
        int nq = m >> 4, ntl = (m >> 3) & 1, ng = m & 7;
        int f4 = (kk * 4 + nq) * 32 + ng * 4 + tgk;
        g_w2h[f4 * 8 + ntl * 4 + half * 2 + h] = __float2half_rn(__ldg(W2 + i));
    }
}

extern __shared__ float smem[];

// 4 k16-steps over one converted 64-k stage; A already fp16 in XH.
__device__ __forceinline__ void mma_stage(const uint32_t* __restrict__ xh,
                                          const uint32_t* __restrict__ w1f,
                                          int kkbase, int base, int nq,
                                          int lane, int g, int tg,
                                          float acc[2][4][4])
{
    const int asw = g << 2;
    #pragma unroll
    for (int kk2 = 0; kk2 < 4; kk2++) {
        const int kk = kkbase + kk2;
        const int k0 = kk * 8;
        const int c0 = (k0 + tg) ^ asw;
        const int c1 = (k0 + tg + 4) ^ asw;
        uint32_t a[2][4];
        #pragma unroll
        for (int mt = 0; mt < 2; mt++) {
            const int r1 = (base + mt * 16 + g) * 128;
            const int r2 = (base + mt * 16 + g + 8) * 128;
            a[mt][0] = xh[r1 + c0];
            a[mt][1] = xh[r2 + c0];
            a[mt][2] = xh[r1 + c1];
            a[mt][3] = xh[r2 + c1];
        }
        const uint4 bfA = *reinterpret_cast<const uint4*>(
            w1f + ((((kk * 4 + nq) * 2 + 0) * 32) + lane) * 4);
        const uint4 bfB = *reinterpret_cast<const uint4*>(
            w1f + ((((kk * 4 + nq) * 2 + 1) * 32) + lane) * 4);
        #pragma unroll
        for (int mt = 0; mt < 2; mt++) {
            mma_f16(acc[mt][0], a[mt][0], a[mt][1], a[mt][2], a[mt][3], bfA.x, bfA.y);
            mma_f16(acc[mt][1], a[mt][0], a[mt][1], a[mt][2], a[mt][3], bfA.z, bfA.w);
            mma_f16(acc[mt][2], a[mt][0], a[mt][1], a[mt][2], a[mt][3], bfB.x, bfB.y);
            mma_f16(acc[mt][3], a[mt][0], a[mt][1], a[mt][2], a[mt][3], bfB.z, bfB.w);
        }
    }
}

__global__ void __launch_bounds__(NTHREADS, 1) lp_tc(
    const float* __restrict__ z,
    const int*   __restrict__ ei,
    const float* __restrict__ W1,
    const float* __restrict__ b1,
    const float* __restrict__ b2,
    const float* __restrict__ W3,
    const float* __restrict__ b3,
    float* __restrict__ out,
    int E, int n_nodes, int ntiles)
{
    const int tid  = threadIdx.x;
    const int lane = tid & 31;
    const int wid  = tid >> 5;
    const int tg   = lane & 3;
    const int g    = lane >> 2;
    uint32_t* s32 = reinterpret_cast<uint32_t*>(smem);
    float* part = smem + PART_F;
    const uint32_t smb = smem_u32(smem);

    // ---- one-time: W1 -> smem fragment-major fp16 ----
    {
        __half* w1h = reinterpret_cast<__half*>(s32 + W1F);
        for (int i = tid; i < 256 * 128; i += NTHREADS) {   // i over W1[k][n]
            int k = i >> 7, n = i & 127;
            int kk = k >> 4, klo = k & 15, half = klo >> 3, tgk = (klo >> 1) & 3, h = klo & 1;
            int nqq = n >> 5, ntl = (n >> 3) & 3, ng = n & 7;
            int f4 = ((kk * 4 + nqq) * 2 + (ntl >> 1)) * 32 + ng * 4 + tgk;
            w1h[f4 * 8 + (ntl & 1) * 4 + half * 2 + h] = __float2half_rn(__ldg(W1 + i));
        }
    }

    // warp roles: 20 warps = 5 M-groups (32 edges) x 4 N-quarters
    const int wm  = wid >> 2;
    const int nq  = wid & 3;
    const int base = wm * 32;
    const int nb1 = nq * 32;
    const int nb2 = nq * 16;

    float b1f[4][2], b2f[2][2], w3f[2][2];
    #pragma unroll
    for (int nt = 0; nt < 4; nt++) {
        b1f[nt][0] = __ldg(b1 + nb1 + nt * 8 + 2 * tg);
        b1f[nt][1] = __ldg(b1 + nb1 + nt * 8 + 2 * tg + 1);
    }
    #pragma unroll
    for (int nt = 0; nt < 2; nt++) {
        b2f[nt][0] = __ldg(b2 + nb2 + nt * 8 + 2 * tg);
        b2f[nt][1] = __ldg(b2 + nb2 + nt * 8 + 2 * tg + 1);
        w3f[nt][0] = __ldg(W3 + nb2 + nt * 8 + 2 * tg);
        w3f[nt][1] = __ldg(W3 + nb2 + nt * 8 + 2 * tg + 1);
    }
    const float b3v = __ldg(b3);

    // gather role: 4 threads per edge, each stages 16 f32 of a 64-col stage slice
    const int ge  = tid >> 2;
    const int gq  = tid & 3;
    const int gsw = (ge & 7) << 2;

    const uint32_t xa_s = smb + XA_F * 4;
    const uint32_t xb_s = smb + XB_F * 4;
    uint32_t* xh = s32 + XH_F;

    int csrc = 0, cdst = 0;
    {
        long long eid = (long long)blockIdx.x * TILE_E + ge;
        if (eid >= (long long)E) eid = (long long)E - 1;
        csrc = min(max(__ldg(ei + eid), 0), n_nodes - 1);
        cdst = min(max(__ldg(ei + (long long)E + eid), 0), n_nodes - 1);
    }
    __syncthreads();

    auto issue = [&](int s, uint32_t buf_s, int src, int dst) {
        const int node = (s < 2) ? src : dst;
        const float* gp = z + (size_t)node * 128 + (s & 1) * 64 + gq * 16;
        #pragma unroll
        for (int j = 0; j < 4; j++)
            cpa16(buf_s + (ge * 64 + ((gq * 16 + j * 4) ^ gsw)) * 4, gp + j * 4);
    };
    // convert own 16 staged f32 -> 8 half2 words in XH at k-range s*64..
    auto cvt_stage = [&](const uint32_t* stf, int s) {
        uint32_t w[8];
        #pragma unroll
        for (int j = 0; j < 4; j++) {
            const uint4 v = *reinterpret_cast<const uint4*>(
                stf + ge * 64 + ((gq * 16 + j * 4) ^ gsw));
            w[j*2+0] = packh2(__uint_as_float(v.x), __uint_as_float(v.y));
            w[j*2+1] = packh2(__uint_as_float(v.z), __uint_as_float(v.w));
        }
        uint32_t* dst0 = xh + ge * 128 + ((s * 32 + gq * 8) ^ gsw);
        uint32_t* dst1 = xh + ge * 128 + ((s * 32 + gq * 8 + 4) ^ gsw);
        *reinterpret_cast<uint4*>(dst0) = make_uint4(w[0], w[1], w[2], w[3]);
        *reinterpret_cast<uint4*>(dst1) = make_uint4(w[4], w[5], w[6], w[7]);
    };

    // prologue: stage 0 of first tile
    issue(0, xa_s, csrc, cdst);
    CPA_COMMIT();

    for (int tile = blockIdx.x; tile < ntiles; tile += gridDim.x) {
        const long long e0 = (long long)tile * TILE_E;
        const int tn = tile + gridDim.x;
        const bool hn = tn < ntiles;

        float acc[2][4][4];
        #pragma unroll
        for (int mt = 0; mt < 2; mt++)
            #pragma unroll
            for (int nt = 0; nt < 4; nt++)
                #pragma unroll
                for (int q = 0; q < 4; q++) acc[mt][nt][q] = 0.f;

        issue(1, xb_s, csrc, cdst); CPA_COMMIT();
        CPA_WAIT(1); cvt_stage(s32 + XA_F, 0); __syncthreads();     // s0 fp16 ready
        issue(2, xa_s, csrc, cdst); CPA_COMMIT();
        mma_stage(xh, s32 + W1F, 0, base, nq, lane, g, tg, acc);

        CPA_WAIT(1); cvt_stage(s32 + XB_F, 1); __syncthreads();     // s1 ready
        issue(3, xb_s, csrc, cdst); CPA_COMMIT();
        mma_stage(xh, s32 + W1F, 4, base, nq, lane, g, tg, acc);

        CPA_WAIT(1); cvt_stage(s32 + XA_F, 2); __syncthreads();     // s2 ready
        mma_stage(xh, s32 + W1F, 8, base, nq, lane, g, tg, acc);

        CPA_WAIT(0); cvt_stage(s32 + XB_F, 3); __syncthreads();     // s3 ready
        mma_stage(xh, s32 + W1F, 12, base, nq, lane, g, tg, acc);
        __syncthreads();                                            // all X reads done

        // ---- h1 = fp16(relu(acc + b1)) -> XH rows (stride 64 words) ----
        #pragma unroll
        for (int mt = 0; mt < 2; mt++) {
            const int rw1 = (base + mt * 16 + g) * 64;
            const int rw2 = (base + mt * 16 + g + 8) * 64;
            #pragma unroll
            for (int nt = 0; nt < 4; nt++) {
                const int j = (nq * 16 + nt * 4 + tg) ^ (g << 2);
                xh[rw1 + j] = packh2(fmaxf(acc[mt][nt][0] + b1f[nt][0], 0.f),
                                     fmaxf(acc[mt][nt][1] + b1f[nt][1], 0.f));
                xh[rw2 + j] = packh2(fmaxf(acc[mt][nt][2] + b1f[nt][0], 0.f),
                                     fmaxf(acc[mt][nt][3] + b1f[nt][1], 0.f));
            }
        }
        __syncthreads();

        // ---- layer 2: C[32 x 16] = H1 @ W2, K=128 (8 k16-steps) ----
        float acc2[2][2][4];
        #pragma unroll
        for (int mt = 0; mt < 2; mt++)
            #pragma unroll
            for (int nt = 0; nt < 2; nt++)
                #pragma unroll
                for (int q = 0; q < 4; q++) acc2[mt][nt][q] = 0.f;
        {
            const int asw = g << 2;
            #pragma unroll 4
            for (int kk = 0; kk < 8; kk++) {
                const int k0 = kk * 8;
                const int c0 = (k0 + tg) ^ asw;
                const int c1 = (k0 + tg + 4) ^ asw;
                uint32_t a[2][4];
                #pragma unroll
                for (int mt = 0; mt < 2; mt++) {
                    const int r1 = (base + mt * 16 + g) * 64;
                    const int r2 = (base + mt * 16 + g + 8) * 64;
                    a[mt][0] = xh[r1 + c0];
                    a[mt][1] = xh[r2 + c0];
                    a[mt][2] = xh[r1 + c1];
                    a[mt][3] = xh[r2 + c1];
                }
                const uint4 bf = __ldg(reinterpret_cast<const uint4*>(
                    reinterpret_cast<const uint32_t*>(g_w2h) + (((kk * 4 + nq) * 32) + lane) * 4));
                #pragma unroll
                for (int mt = 0; mt < 2; mt++) {
                    mma_f16(acc2[mt][0], a[mt][0], a[mt][1], a[mt][2], a[mt][3], bf.x, bf.y);
                    mma_f16(acc2[mt][1], a[mt][0], a[mt][1], a[mt][2], a[mt][3], bf.z, bf.w);
                }
            }
        }
        __syncthreads();   // h1 reads done before next tile's conversion writes XH

        // ---- prefetch next tile: indices + stage 0 -> XA f32 (overlaps epilogue) ----
        if (hn) {
            long long eid = (long long)tn * TILE_E + ge;
            if (eid >= (long long)E) eid = (long long)E - 1;
            csrc = min(max(__ldg(ei + eid), 0), n_nodes - 1);
            cdst = min(max(__ldg(ei + (long long)E + eid), 0), n_nodes - 1);
            issue(0, xa_s, csrc, cdst);
        }
        CPA_COMMIT();

        // ---- layer 3: dot with W3, shfl reduce over tg, combine ----
        #pragma unroll
        for (int mt = 0; mt < 2; mt++) {
            float p0 = 0.f, p1 = 0.f;
            #pragma unroll
            for (int nt = 0; nt < 2; nt++) {
                p0 += fmaxf(acc2[mt][nt][0] + b2f[nt][0], 0.f) * w3f[nt][0]
                    + fmaxf(acc2[mt][nt][1] + b2f[nt][1], 0.f) * w3f[nt][1];
                p1 += fmaxf(acc2[mt][nt][2] + b2f[nt][0], 0.f) * w3f[nt][0]
                    + fmaxf(acc2[mt][nt][3] + b2f[nt][1], 0.f) * w3f[nt][1];
            }
            p0 += __shfl_xor_sync(0xffffffffu, p0, 1);
            p0 += __shfl_xor_sync(0xffffffffu, p0, 2);
            p1 += __shfl_xor_sync(0xffffffffu, p1, 1);
            p1 += __shfl_xor_sync(0xffffffffu, p1, 2);
            if (tg == 0) {
                part[(base + mt * 16 + g) * 4 + nq]     = p0;
                part[(base + mt * 16 + g + 8) * 4 + nq] = p1;
            }
        }
        __syncthreads();

        if (tid < TILE_E) {
            long long eid = e0 + tid;
            if (eid < (long long)E)
                out[eid] = part[tid * 4] + part[tid * 4 + 1]
                         + part[tid * 4 + 2] + part[tid * 4 + 3] + b3v;
        }
    }
}

extern "C" void kernel_launch(void* const* d_in, const int* in_sizes, int n_in,
                              void* d_out, int out_size)
{
    const float* z  = (const float*)d_in[0];
    const int*   ei = (const int*)d_in[1];
    const float* W1 = (const float*)d_in[2];
    const float* b1 = (const float*)d_in[3];
    const float* W2 = (const float*)d_in[4];
    const float* b2 = (const float*)d_in[5];
    const float* W3 = (const float*)d_in[6];
    const float* b3 = (const float*)d_in[7];
    float* out = (float*)d_out;

    const int E       = in_sizes[1] / 2;
    const int n_nodes = in_sizes[0] / 128;
    const int ntiles  = (E + TILE_E - 1) / TILE_E;
    const int smem_bytes = SMEM_W * 4;   // 231936 B

    static bool attr_set = false;
    if (!attr_set) {
        cudaFuncSetAttribute(lp_tc, cudaFuncAttributeMaxDynamicSharedMemorySize, smem_bytes);
        attr_set = true;
    }

    repack_w2<<<16, 512>>>(W2);

    int grid = 148;
    if (grid > ntiles) grid = ntiles;
    lp_tc<<<grid, NTHREADS, smem_bytes>>>(z, ei, W1, b1, b2, W3, b3, out, E, n_nodes, ntiles);
}

// round 12
// speedup vs baseline: 2.9459x; 1.3758x over previous
#include <cuda_runtime.h>
#include <cuda_fp16.h>
#include <cstdint>

#define TILE_E   160
#define NTHREADS 640
#define N_NODES_MAX 50000

// smem layout in 4-byte words
#define W1F    0        // 16384 : W1 fragment-major fp16 (64 KB)
#define XH_F   16384    // 20480 : fp16 X (160 rows x 128 half2 words), cp.async target (80 KB)
#define H1_F   36864    // 10240 : fp16 h1 (160 rows x 64 half2 words) (40 KB)
#define PART_F 47104    // 640 floats
#define SMEM_W 47744    // * 4 = 190976 B

__device__ __align__(16) __half g_w2h[128 * 64];                 // W2 fragment-major fp16
__device__ __align__(16) __half g_zh[(size_t)N_NODES_MAX * 128]; // z pre-quantized fp16 (12.8 MB)

__device__ __forceinline__ uint32_t smem_u32(const void* p) {
    uint32_t a; asm("{ .reg .u64 t; cvta.to.shared.u64 t, %1; cvt.u32.u64 %0, t; }" : "=r"(a) : "l"(p));
    return a;
}
__device__ __forceinline__ void mma_f16(float c[4],
    uint32_t a0, uint32_t a1, uint32_t a2, uint32_t a3, uint32_t b0, uint32_t b1)
{
    asm volatile("mma.sync.aligned.m16n8k16.row.col.f32.f16.f16.f32 "
        "{%0,%1,%2,%3}, {%4,%5,%6,%7}, {%8,%9}, {%0,%1,%2,%3};"
        : "+f"(c[0]), "+f"(c[1]), "+f"(c[2]), "+f"(c[3])
        : "r"(a0), "r"(a1), "r"(a2), "r"(a3), "r"(b0), "r"(b1));
}
__device__ __forceinline__ void cpa16(uint32_t s, const void* g) {
    asm volatile("cp.async.cg.shared.global [%0], [%1], 16;" :: "r"(s), "l"(g));
}
#define CPA_COMMIT() asm volatile("cp.async.commit_group;" ::: "memory")
#define CPA_WAIT(n)  asm volatile("cp.async.wait_group %0;" :: "n"(n) : "memory")

__device__ __forceinline__ uint32_t packh2(float lo, float hi) {
    __half2 h = __floats2half2_rn(lo, hi);
    return *reinterpret_cast<uint32_t*>(&h);
}

__global__ void repack_w2(const float* __restrict__ W2) {
    int i = blockIdx.x * blockDim.x + threadIdx.x;   // i over W2[k][m]
    if (i < 128 * 64) {
        int k = i >> 6, m = i & 63;
        int kk = k >> 4, klo = k & 15, half = klo >> 3, tgk = (klo >> 1) & 3, h = klo & 1;
        int nq = m >> 4, ntl = (m >> 3) & 1, ng = m & 7;
        int f4 = (kk * 4 + nq) * 32 + ng * 4 + tgk;
        g_w2h[f4 * 8 + ntl * 4 + half * 2 + h] = __float2half_rn(__ldg(W2 + i));
    }
}

__global__ void quant_z(const float* __restrict__ z, int n) {   // n = n_nodes*64 float2 pairs
    int i = blockIdx.x * blockDim.x + threadIdx.x;
    if (i < n) {
        float2 v = __ldg((const float2*)z + i);
        reinterpret_cast<__half2*>(g_zh)[i] = __floats2half2_rn(v.x, v.y);
    }
}

extern __shared__ float smem[];

// 4 k16-steps over one 64-half stage; A fp16 in XH (row stride 128 words).
__device__ __forceinline__ void mma_stage(const uint32_t* __restrict__ xh,
                                          const uint32_t* __restrict__ w1f,
                                          int kkbase, int base, int nq,
                                          int lane, int g, int tg,
                                          float acc[2][4][4])
{
    const int asw = g << 2;
    #pragma unroll
    for (int kk2 = 0; kk2 < 4; kk2++) {
        const int kk = kkbase + kk2;
        const int k0 = kk * 8;
        const int c0 = (k0 + tg) ^ asw;
        const int c1 = (k0 + tg + 4) ^ asw;
        uint32_t a[2][4];
        #pragma unroll
        for (int mt = 0; mt < 2; mt++) {
            const int r1 = (base + mt * 16 + g) * 128;
            const int r2 = (base + mt * 16 + g + 8) * 128;
            a[mt][0] = xh[r1 + c0];
            a[mt][1] = xh[r2 + c0];
            a[mt][2] = xh[r1 + c1];
            a[mt][3] = xh[r2 + c1];
        }
        const uint4 bfA = *reinterpret_cast<const uint4*>(
            w1f + ((((kk * 4 + nq) * 2 + 0) * 32) + lane) * 4);
        const uint4 bfB = *reinterpret_cast<const uint4*>(
            w1f + ((((kk * 4 + nq) * 2 + 1) * 32) + lane) * 4);
        #pragma unroll
        for (int mt = 0; mt < 2; mt++) {
            mma_f16(acc[mt][0], a[mt][0], a[mt][1], a[mt][2], a[mt][3], bfA.x, bfA.y);
            mma_f16(acc[mt][1], a[mt][0], a[mt][1], a[mt][2], a[mt][3], bfA.z, bfA.w);
            mma_f16(acc[mt][2], a[mt][0], a[mt][1], a[mt][2], a[mt][3], bfB.x, bfB.y);
            mma_f16(acc[mt][3], a[mt][0], a[mt][1], a[mt][2], a[mt][3], bfB.z, bfB.w);
        }
    }
}

__global__ void __launch_bounds__(NTHREADS, 1) lp_tc(
    const int*   __restrict__ ei,
    const float* __restrict__ W1,
    const float* __restrict__ b1,
    const float* __restrict__ b2,
    const float* __restrict__ W3,
    const float* __restrict__ b3,
    float* __restrict__ out,
    int E, int n_nodes, int ntiles)
{
    const int tid  = threadIdx.x;
    const int lane = tid & 31;
    const int wid  = tid >> 5;
    const int tg   = lane & 3;
    const int g    = lane >> 2;
    uint32_t* s32 = reinterpret_cast<uint32_t*>(smem);
    float* part = smem + PART_F;
    const uint32_t smb = smem_u32(smem);

    // ---- one-time: W1 -> smem fragment-major fp16 ----
    {
        __half* w1h = reinterpret_cast<__half*>(s32 + W1F);
        for (int i = tid; i < 256 * 128; i += NTHREADS) {   // i over W1[k][n]
            int k = i >> 7, n = i & 127;
            int kk = k >> 4, klo = k & 15, half = klo >> 3, tgk = (klo >> 1) & 3, h = klo & 1;
            int nqq = n >> 5, ntl = (n >> 3) & 3, ng = n & 7;
            int f4 = ((kk * 4 + nqq) * 2 + (ntl >> 1)) * 32 + ng * 4 + tgk;
            w1h[f4 * 8 + (ntl & 1) * 4 + half * 2 + h] = __float2half_rn(__ldg(W1 + i));
        }
    }

    // warp roles: 20 warps = 5 M-groups (32 edges) x 4 N-quarters
    const int wm  = wid >> 2;
    const int nq  = wid & 3;
    const int base = wm * 32;
    const int nb1 = nq * 32;
    const int nb2 = nq * 16;

    float b1f[4][2], b2f[2][2], w3f[2][2];
    #pragma unroll
    for (int nt = 0; nt < 4; nt++) {
        b1f[nt][0] = __ldg(b1 + nb1 + nt * 8 + 2 * tg);
        b1f[nt][1] = __ldg(b1 + nb1 + nt * 8 + 2 * tg + 1);
    }
    #pragma unroll
    for (int nt = 0; nt < 2; nt++) {
        b2f[nt][0] = __ldg(b2 + nb2 + nt * 8 + 2 * tg);
        b2f[nt][1] = __ldg(b2 + nb2 + nt * 8 + 2 * tg + 1);
        w3f[nt][0] = __ldg(W3 + nb2 + nt * 8 + 2 * tg);
        w3f[nt][1] = __ldg(W3 + nb2 + nt * 8 + 2 * tg + 1);
    }
    const float b3v = __ldg(b3);

    // gather role: 4 threads per edge; per stage each stages 16 halves (32 B = 2 chunks)
    const int ge  = tid >> 2;
    const int gq  = tid & 3;
    const int gsw = (ge & 7) << 2;

    uint32_t* xh = s32 + XH_F;
    uint32_t* h1 = s32 + H1_F;

    int csrc = 0, cdst = 0;
    {
        long long eid = (long long)blockIdx.x * TILE_E + ge;
        if (eid >= (long long)E) eid = (long long)E - 1;
        csrc = min(max(__ldg(ei + eid), 0), n_nodes - 1);
        cdst = min(max(__ldg(ei + (long long)E + eid), 0), n_nodes - 1);
    }
    __syncthreads();   // W1 repack visible before first MMA

    // stage s: 0=src lo64, 1=src hi64, 2=dst lo64, 3=dst hi64 (halves)
    auto issue = [&](int s, int src, int dst) {
        const int node = (s < 2) ? src : dst;
        const __half* gp = g_zh + (size_t)node * 128 + (s & 1) * 64 + gq * 16;
        #pragma unroll
        for (int j = 0; j < 2; j++)
            cpa16(smb + (XH_F + ge * 128 + ((s * 32 + gq * 8 + j * 4) ^ gsw)) * 4, gp + j * 8);
    };

    // prologue: stage 0 of first tile
    issue(0, csrc, cdst);
    CPA_COMMIT();

    for (int tile = blockIdx.x; tile < ntiles; tile += gridDim.x) {
        const long long e0 = (long long)tile * TILE_E;
        const int tn = tile + gridDim.x;
        const bool hn = tn < ntiles;

        // issue remaining stages as separate groups
        issue(1, csrc, cdst); CPA_COMMIT();
        issue(2, csrc, cdst); CPA_COMMIT();
        issue(3, csrc, cdst); CPA_COMMIT();

        float acc[2][4][4];
        #pragma unroll
        for (int mt = 0; mt < 2; mt++)
            #pragma unroll
            for (int nt = 0; nt < 4; nt++)
                #pragma unroll
                for (int q = 0; q < 4; q++) acc[mt][nt][q] = 0.f;

        CPA_WAIT(3); __syncthreads();
        mma_stage(xh, s32 + W1F, 0, base, nq, lane, g, tg, acc);
        CPA_WAIT(2); __syncthreads();
        mma_stage(xh, s32 + W1F, 4, base, nq, lane, g, tg, acc);
        CPA_WAIT(1); __syncthreads();
        mma_stage(xh, s32 + W1F, 8, base, nq, lane, g, tg, acc);
        CPA_WAIT(0); __syncthreads();
        mma_stage(xh, s32 + W1F, 12, base, nq, lane, g, tg, acc);
        __syncthreads();                     // all XH reads done

        // prefetch next tile: indices + stage 0 -> XH (overlaps h1/layer2/layer3)
        if (hn) {
            long long eid = (long long)tn * TILE_E + ge;
            if (eid >= (long long)E) eid = (long long)E - 1;
            csrc = min(max(__ldg(ei + eid), 0), n_nodes - 1);
            cdst = min(max(__ldg(ei + (long long)E + eid), 0), n_nodes - 1);
            issue(0, csrc, cdst);
        }
        CPA_COMMIT();

        // ---- h1 = fp16(relu(acc + b1)) -> H1 (row stride 64 words) ----
        #pragma unroll
        for (int mt = 0; mt < 2; mt++) {
            const int rw1 = (base + mt * 16 + g) * 64;
            const int rw2 = (base + mt * 16 + g + 8) * 64;
            #pragma unroll
            for (int nt = 0; nt < 4; nt++) {
                const int j = (nq * 16 + nt * 4 + tg) ^ (g << 2);
                h1[rw1 + j] = packh2(fmaxf(acc[mt][nt][0] + b1f[nt][0], 0.f),
                                     fmaxf(acc[mt][nt][1] + b1f[nt][1], 0.f));
                h1[rw2 + j] = packh2(fmaxf(acc[mt][nt][2] + b1f[nt][0], 0.f),
                                     fmaxf(acc[mt][nt][3] + b1f[nt][1], 0.f));
            }
        }
        __syncthreads();

        // ---- layer 2: C[32 x 16] = H1 @ W2, K=128 (8 k16-steps) ----
        float acc2[2][2][4];
        #pragma unroll
        for (int mt = 0; mt < 2; mt++)
            #pragma unroll
            for (int nt = 0; nt < 2; nt++)
                #pragma unroll
                for (int q = 0; q < 4; q++) acc2[mt][nt][q] = 0.f;
        {
            const int asw = g << 2;
            #pragma unroll 4
            for (int kk = 0; kk < 8; kk++) {
                const int k0 = kk * 8;
                const int c0 = (k0 + tg) ^ asw;
                const int c1 = (k0 + tg + 4) ^ asw;
                uint32_t a[2][4];
                #pragma unroll
                for (int mt = 0; mt < 2; mt++) {
                    const int r1 = (base + mt * 16 + g) * 64;
                    const int r2 = (base + mt * 16 + g + 8) * 64;
                    a[mt][0] = h1[r1 + c0];
                    a[mt][1] = h1[r2 + c0];
                    a[mt][2] = h1[r1 + c1];
                    a[mt][3] = h1[r2 + c1];
                }
                const uint4 bf = __ldg(reinterpret_cast<const uint4*>(
                    reinterpret_cast<const uint32_t*>(g_w2h) + (((kk * 4 + nq) * 32) + lane) * 4));
                #pragma unroll
                for (int mt = 0; mt < 2; mt++) {
                    mma_f16(acc2[mt][0], a[mt][0], a[mt][1], a[mt][2], a[mt][3], bf.x, bf.y);
                    mma_f16(acc2[mt][1], a[mt][0], a[mt][1], a[mt][2], a[mt][3], bf.z, bf.w);
                }
            }
        }

        // ---- layer 3: dot with W3, shfl reduce over tg, combine ----
        #pragma unroll
        for (int mt = 0; mt < 2; mt++) {
            float p0 = 0.f, p1 = 0.f;
            #pragma unroll
            for (int nt = 0; nt < 2; nt++) {
                p0 += fmaxf(acc2[mt][nt][0] + b2f[nt][0], 0.f) * w3f[nt][0]
                    + fmaxf(acc2[mt][nt][1] + b2f[nt][1], 0.f) * w3f[nt][1];
                p1 += fmaxf(acc2[mt][nt][2] + b2f[nt][0], 0.f) * w3f[nt][0]
                    + fmaxf(acc2[mt][nt][3] + b2f[nt][1], 0.f) * w3f[nt][1];
            }
            p0 += __shfl_xor_sync(0xffffffffu, p0, 1);
            p0 += __shfl_xor_sync(0xffffffffu, p0, 2);
            p1 += __shfl_xor_sync(0xffffffffu, p1, 1);
            p1 += __shfl_xor_sync(0xffffffffu, p1, 2);
            if (tg == 0) {
                part[(base + mt * 16 + g) * 4 + nq]     = p0;
                part[(base + mt * 16 + g + 8) * 4 + nq] = p1;
            }
        }
        __syncthreads();

        if (tid < TILE_E) {
            long long eid = e0 + tid;
            if (eid < (long long)E)
                out[eid] = part[tid * 4] + part[tid * 4 + 1]
                         + part[tid * 4 + 2] + part[tid * 4 + 3] + b3v;
        }
        __syncthreads();   // part reads done before next tile's writers
    }
}

extern "C" void kernel_launch(void* const* d_in, const int* in_sizes, int n_in,
                              void* d_out, int out_size)
{
    const float* z  = (const float*)d_in[0];
    const int*   ei = (const int*)d_in[1];
    const float* W1 = (const float*)d_in[2];
    const float* b1 = (const float*)d_in[3];
    const float* W2 = (const float*)d_in[4];
    const float* b2 = (const float*)d_in[5];
    const float* W3 = (const float*)d_in[6];
    const float* b3 = (const float*)d_in[7];
    float* out = (float*)d_out;

    const int E       = in_sizes[1] / 2;
    int n_nodes       = in_sizes[0] / 128;
    if (n_nodes > N_NODES_MAX) n_nodes = N_NODES_MAX;
    const int ntiles  = (E + TILE_E - 1) / TILE_E;
    const int smem_bytes = SMEM_W * 4;   // 190976 B

    static bool attr_set = false;
    if (!attr_set) {
        cudaFuncSetAttribute(lp_tc, cudaFuncAttributeMaxDynamicSharedMemorySize, smem_bytes);
        attr_set = true;
    }

    repack_w2<<<16, 512>>>(W2);
    const int npairs = n_nodes * 64;
    quant_z<<<(npairs + 255) / 256, 256>>>(z, npairs);

    int grid = 148;
    if (grid > ntiles) grid = ntiles;
    lp_tc<<<grid, NTHREADS, smem_bytes>>>(ei, W1, b1, b2, W3, b3, out, E, n_nodes, ntiles);
}

// round 13
// speedup vs baseline: 3.1110x; 1.0560x over previous
#include <cuda_runtime.h>
#include <cuda_fp16.h>
#include <cstdint>

#define TILE_E   160
#define NTHREADS 640
#define N_NODES_MAX 50000

// smem layout in 4-byte words
#define W1F    0        // 16384 : W1 fragment-major fp16 (64 KB)
#define XH_F   16384    // 20480 : fp16 X (160 rows x 128 half2 words), cp.async target (80 KB)
#define H1_F   36864    // 10240 : fp16 h1 (160 rows x 64 half2 words) (40 KB)
#define PART_F 47104    // 640 floats
#define SMEM_W 47744    // * 4 = 190976 B

__device__ __align__(16) __half g_w2h[128 * 64];                 // W2 fragment-major fp16
__device__ __align__(16) __half g_zh[(size_t)N_NODES_MAX * 128]; // z pre-quantized fp16 (12.8 MB)

__device__ __forceinline__ uint32_t smem_u32(const void* p) {
    uint32_t a; asm("{ .reg .u64 t; cvta.to.shared.u64 t, %1; cvt.u32.u64 %0, t; }" : "=r"(a) : "l"(p));
    return a;
}
__device__ __forceinline__ void mma_f16(float c[4],
    uint32_t a0, uint32_t a1, uint32_t a2, uint32_t a3, uint32_t b0, uint32_t b1)
{
    asm volatile("mma.sync.aligned.m16n8k16.row.col.f32.f16.f16.f32 "
        "{%0,%1,%2,%3}, {%4,%5,%6,%7}, {%8,%9}, {%0,%1,%2,%3};"
        : "+f"(c[0]), "+f"(c[1]), "+f"(c[2]), "+f"(c[3])
        : "r"(a0), "r"(a1), "r"(a2), "r"(a3), "r"(b0), "r"(b1));
}
__device__ __forceinline__ void cpa16(uint32_t s, const void* g) {
    asm volatile("cp.async.cg.shared.global [%0], [%1], 16;" :: "r"(s), "l"(g));
}
#define CPA_COMMIT() asm volatile("cp.async.commit_group;" ::: "memory")
#define CPA_WAIT(n)  asm volatile("cp.async.wait_group %0;" :: "n"(n) : "memory")

__device__ __forceinline__ uint32_t packh2(float lo, float hi) {
    __half2 h = __floats2half2_rn(lo, hi);
    return *reinterpret_cast<uint32_t*>(&h);
}

// merged setup: W2 repack + z quantization in one launch
__global__ void prep(const float* __restrict__ z, const float* __restrict__ W2, int npairs) {
    int i = blockIdx.x * blockDim.x + threadIdx.x;
    if (i < 128 * 64) {
        int k = i >> 6, m = i & 63;
        int kk = k >> 4, klo = k & 15, half = klo >> 3, tgk = (klo >> 1) & 3, h = klo & 1;
        int nq = m >> 4, ntl = (m >> 3) & 1, ng = m & 7;
        int f4 = (kk * 4 + nq) * 32 + ng * 4 + tgk;
        g_w2h[f4 * 8 + ntl * 4 + half * 2 + h] = __float2half_rn(__ldg(W2 + i));
    }
    if (i < npairs) {
        float2 v = __ldg((const float2*)z + i);
        reinterpret_cast<__half2*>(g_zh)[i] = __floats2half2_rn(v.x, v.y);
    }
}

extern __shared__ float smem[];

// 4 k16-steps over one 64-half stage; A fp16 in XH (row stride 128 words).
__device__ __forceinline__ void mma_stage(const uint32_t* __restrict__ xh,
                                          const uint32_t* __restrict__ w1f,
                                          int kkbase, int base, int nq,
                                          int lane, int g, int tg,
                                          float acc[2][4][4])
{
    const int asw = g << 2;
    #pragma unroll
    for (int kk2 = 0; kk2 < 4; kk2++) {
        const int kk = kkbase + kk2;
        const int k0 = kk * 8;
        const int c0 = (k0 + tg) ^ asw;
        const int c1 = (k0 + tg + 4) ^ asw;
        uint32_t a[2][4];
        #pragma unroll
        for (int mt = 0; mt < 2; mt++) {
            const int r1 = (base + mt * 16 + g) * 128;
            const int r2 = (base + mt * 16 + g + 8) * 128;
            a[mt][0] = xh[r1 + c0];
            a[mt][1] = xh[r2 + c0];
            a[mt][2] = xh[r1 + c1];
            a[mt][3] = xh[r2 + c1];
        }
        const uint4 bfA = *reinterpret_cast<const uint4*>(
            w1f + ((((kk * 4 + nq) * 2 + 0) * 32) + lane) * 4);
        const uint4 bfB = *reinterpret_cast<const uint4*>(
            w1f + ((((kk * 4 + nq) * 2 + 1) * 32) + lane) * 4);
        #pragma unroll
        for (int mt = 0; mt < 2; mt++) {
            mma_f16(acc[mt][0], a[mt][0], a[mt][1], a[mt][2], a[mt][3], bfA.x, bfA.y);
            mma_f16(acc[mt][1], a[mt][0], a[mt][1], a[mt][2], a[mt][3], bfA.z, bfA.w);
            mma_f16(acc[mt][2], a[mt][0], a[mt][1], a[mt][2], a[mt][3], bfB.x, bfB.y);
            mma_f16(acc[mt][3], a[mt][0], a[mt][1], a[mt][2], a[mt][3], bfB.z, bfB.w);
        }
    }
}

__global__ void __launch_bounds__(NTHREADS, 1) lp_tc(
    const int*   __restrict__ ei,
    const float* __restrict__ W1,
    const float* __restrict__ b1,
    const float* __restrict__ b2,
    const float* __restrict__ W3,
    const float* __restrict__ b3,
    float* __restrict__ out,
    int E, int n_nodes, int ntiles)
{
    const int tid  = threadIdx.x;
    const int lane = tid & 31;
    const int wid  = tid >> 5;
    const int tg   = lane & 3;
    const int g    = lane >> 2;
    uint32_t* s32 = reinterpret_cast<uint32_t*>(smem);
    float* part = smem + PART_F;
    const uint32_t smb = smem_u32(smem);

    // ---- one-time: W1 -> smem fragment-major fp16 ----
    {
        __half* w1h = reinterpret_cast<__half*>(s32 + W1F);
        for (int i = tid; i < 256 * 128; i += NTHREADS) {   // i over W1[k][n]
            int k = i >> 7, n = i & 127;
            int kk = k >> 4, klo = k & 15, half = klo >> 3, tgk = (klo >> 1) & 3, h = klo & 1;
            int nqq = n >> 5, ntl = (n >> 3) & 3, ng = n & 7;
            int f4 = ((kk * 4 + nqq) * 2 + (ntl >> 1)) * 32 + ng * 4 + tgk;
            w1h[f4 * 8 + (ntl & 1) * 4 + half * 2 + h] = __float2half_rn(__ldg(W1 + i));
        }
    }

    // warp roles: 20 warps = 5 M-groups (32 edges) x 4 N-quarters
    const int wm  = wid >> 2;
    const int nq  = wid & 3;
    const int base = wm * 32;
    const int nb1 = nq * 32;
    const int nb2 = nq * 16;

    float b1f[4][2], b2f[2][2], w3f[2][2];
    #pragma unroll
    for (int nt = 0; nt < 4; nt++) {
        b1f[nt][0] = __ldg(b1 + nb1 + nt * 8 + 2 * tg);
        b1f[nt][1] = __ldg(b1 + nb1 + nt * 8 + 2 * tg + 1);
    }
    #pragma unroll
    for (int nt = 0; nt < 2; nt++) {
        b2f[nt][0] = __ldg(b2 + nb2 + nt * 8 + 2 * tg);
        b2f[nt][1] = __ldg(b2 + nb2 + nt * 8 + 2 * tg + 1);
        w3f[nt][0] = __ldg(W3 + nb2 + nt * 8 + 2 * tg);
        w3f[nt][1] = __ldg(W3 + nb2 + nt * 8 + 2 * tg + 1);
    }
    const float b3v = __ldg(b3);

    // gather role: 4 threads per edge; per stage each stages 16 halves (32 B = 2 chunks)
    const int ge  = tid >> 2;
    const int gq  = tid & 3;
    const int gsw = (ge & 7) << 2;

    uint32_t* xh = s32 + XH_F;
    uint32_t* h1 = s32 + H1_F;

    int csrc = 0, cdst = 0;
    {
        long long eid = (long long)blockIdx.x * TILE_E + ge;
        if (eid >= (long long)E) eid = (long long)E - 1;
        csrc = min(max(__ldg(ei + eid), 0), n_nodes - 1);
        cdst = min(max(__ldg(ei + (long long)E + eid), 0), n_nodes - 1);
    }
    __syncthreads();   // W1 repack visible before first MMA

    // stage s: 0=src lo64, 1=src hi64, 2=dst lo64, 3=dst hi64 (halves)
    auto issue = [&](int s, int src, int dst) {
        const int node = (s < 2) ? src : dst;
        const __half* gp = g_zh + (size_t)node * 128 + (s & 1) * 64 + gq * 16;
        #pragma unroll
        for (int j = 0; j < 2; j++)
            cpa16(smb + (XH_F + ge * 128 + ((s * 32 + gq * 8 + j * 4) ^ gsw)) * 4, gp + j * 8);
    };

    // prologue: ALL four stages of first tile (4 commit groups)
    issue(0, csrc, cdst); CPA_COMMIT();
    issue(1, csrc, cdst); CPA_COMMIT();
    issue(2, csrc, cdst); CPA_COMMIT();
    issue(3, csrc, cdst); CPA_COMMIT();

    for (int tile = blockIdx.x; tile < ntiles; tile += gridDim.x) {
        const long long e0 = (long long)tile * TILE_E;
        const int tn = tile + gridDim.x;
        const bool hn = tn < ntiles;

        // prefetch next tile's indices into registers (overlaps layer 1)
        int nsrc = 0, ndst = 0;
        if (hn) {
            long long eid = (long long)tn * TILE_E + ge;
            if (eid >= (long long)E) eid = (long long)E - 1;
            nsrc = min(max(__ldg(ei + eid), 0), n_nodes - 1);
            ndst = min(max(__ldg(ei + (long long)E + eid), 0), n_nodes - 1);
        }

        float acc[2][4][4];
        #pragma unroll
        for (int mt = 0; mt < 2; mt++)
            #pragma unroll
            for (int nt = 0; nt < 4; nt++)
                #pragma unroll
                for (int q = 0; q < 4; q++) acc[mt][nt][q] = 0.f;

        CPA_WAIT(3); __syncthreads();
        mma_stage(xh, s32 + W1F, 0, base, nq, lane, g, tg, acc);
        CPA_WAIT(2); __syncthreads();
        mma_stage(xh, s32 + W1F, 4, base, nq, lane, g, tg, acc);
        CPA_WAIT(1); __syncthreads();
        mma_stage(xh, s32 + W1F, 8, base, nq, lane, g, tg, acc);
        CPA_WAIT(0); __syncthreads();
        mma_stage(xh, s32 + W1F, 12, base, nq, lane, g, tg, acc);
        __syncthreads();                     // all XH reads done

        // issue ALL next-tile stages now — full epilogue hides the gather latency.
        // (4 commit groups always, to keep wait-counting aligned.)
        if (hn) {
            issue(0, nsrc, ndst); CPA_COMMIT();
            issue(1, nsrc, ndst); CPA_COMMIT();
            issue(2, nsrc, ndst); CPA_COMMIT();
            issue(3, nsrc, ndst); CPA_COMMIT();
        } else {
            CPA_COMMIT(); CPA_COMMIT(); CPA_COMMIT(); CPA_COMMIT();
        }

        // ---- h1 = fp16(relu(acc + b1)) -> H1 (row stride 64 words) ----
        #pragma unroll
        for (int mt = 0; mt < 2; mt++) {
            const int rw1 = (base + mt * 16 + g) * 64;
            const int rw2 = (base + mt * 16 + g + 8) * 64;
            #pragma unroll
            for (int nt = 0; nt < 4; nt++) {
                const int j = (nq * 16 + nt * 4 + tg) ^ (g << 2);
                h1[rw1 + j] = packh2(fmaxf(acc[mt][nt][0] + b1f[nt][0], 0.f),
                                     fmaxf(acc[mt][nt][1] + b1f[nt][1], 0.f));
                h1[rw2 + j] = packh2(fmaxf(acc[mt][nt][2] + b1f[nt][0], 0.f),
                                     fmaxf(acc[mt][nt][3] + b1f[nt][1], 0.f));
            }
        }
        __syncthreads();

        // ---- layer 2: C[32 x 16] = H1 @ W2, K=128 (8 k16-steps) ----
        float acc2[2][2][4];
        #pragma unroll
        for (int mt = 0; mt < 2; mt++)
            #pragma unroll
            for (int nt = 0; nt < 2; nt++)
                #pragma unroll
                for (int q = 0; q < 4; q++) acc2[mt][nt][q] = 0.f;
        {
            const int asw = g << 2;
            #pragma unroll 4
            for (int kk = 0; kk < 8; kk++) {
                const int k0 = kk * 8;
                const int c0 = (k0 + tg) ^ asw;
                const int c1 = (k0 + tg + 4) ^ asw;
                uint32_t a[2][4];
                #pragma unroll
                for (int mt = 0; mt < 2; mt++) {
                    const int r1 = (base + mt * 16 + g) * 64;
                    const int r2 = (base + mt * 16 + g + 8) * 64;
                    a[mt][0] = h1[r1 + c0];
                    a[mt][1] = h1[r2 + c0];
                    a[mt][2] = h1[r1 + c1];
                    a[mt][3] = h1[r2 + c1];
                }
                const uint4 bf = __ldg(reinterpret_cast<const uint4*>(
                    reinterpret_cast<const uint32_t*>(g_w2h) + (((kk * 4 + nq) * 32) + lane) * 4));
                #pragma unroll
                for (int mt = 0; mt < 2; mt++) {
                    mma_f16(acc2[mt][0], a[mt][0], a[mt][1], a[mt][2], a[mt][3], bf.x, bf.y);
                    mma_f16(acc2[mt][1], a[mt][0], a[mt][1], a[mt][2], a[mt][3], bf.z, bf.w);
                }
            }
        }

        // ---- layer 3: dot with W3, shfl reduce over tg, combine ----
        #pragma unroll
        for (int mt = 0; mt < 2; mt++) {
            float p0 = 0.f, p1 = 0.f;
            #pragma unroll
            for (int nt = 0; nt < 2; nt++) {
                p0 += fmaxf(acc2[mt][nt][0] + b2f[nt][0], 0.f) * w3f[nt][0]
                    + fmaxf(acc2[mt][nt][1] + b2f[nt][1], 0.f) * w3f[nt][1];
                p1 += fmaxf(acc2[mt][nt][2] + b2f[nt][0], 0.f) * w3f[nt][0]
                    + fmaxf(acc2[mt][nt][3] + b2f[nt][1], 0.f) * w3f[nt][1];
            }
            p0 += __shfl_xor_sync(0xffffffffu, p0, 1);
            p0 += __shfl_xor_sync(0xffffffffu, p0, 2);
            p1 += __shfl_xor_sync(0xffffffffu, p1, 1);
            p1 += __shfl_xor_sync(0xffffffffu, p1, 2);
            if (tg == 0) {
                part[(base + mt * 16 + g) * 4 + nq]     = p0;
                part[(base + mt * 16 + g + 8) * 4 + nq] = p1;
            }
        }
        __syncthreads();

        if (tid < TILE_E) {
            long long eid = e0 + tid;
            if (eid < (long long)E)
                out[eid] = part[tid * 4] + part[tid * 4 + 1]
                         + part[tid * 4 + 2] + part[tid * 4 + 3] + b3v;
        }
        // no trailing barrier: next write to part is behind the stage-wait barriers.
        csrc = nsrc; cdst = ndst;
    }
}

extern "C" void kernel_launch(void* const* d_in, const int* in_sizes, int n_in,
                              void* d_out, int out_size)
{
    const float* z  = (const float*)d_in[0];
    const int*   ei = (const int*)d_in[1];
    const float* W1 = (const float*)d_in[2];
    const float* b1 = (const float*)d_in[3];
    const float* W2 = (const float*)d_in[4];
    const float* b2 = (const float*)d_in[5];
    const float* W3 = (const float*)d_in[6];
    const float* b3 = (const float*)d_in[7];
    float* out = (float*)d_out;

    const int E       = in_sizes[1] / 2;
    int n_nodes       = in_sizes[0] / 128;
    if (n_nodes > N_NODES_MAX) n_nodes = N_NODES_MAX;
    const int ntiles  = (E + TILE_E - 1) / TILE_E;
    const int smem_bytes = SMEM_W * 4;   // 190976 B

    static bool attr_set = false;
    if (!attr_set) {
        cudaFuncSetAttribute(lp_tc, cudaFuncAttributeMaxDynamicSharedMemorySize, smem_bytes);
        attr_set = true;
    }

    const int npairs = n_nodes * 64;
    const int prep_n = (npairs > 128 * 64) ? npairs : 128 * 64;
    prep<<<(prep_n + 255) / 256, 256>>>(z, W2, npairs);

    int grid = 148;
    if (grid > ntiles) grid = ntiles;
    lp_tc<<<grid, NTHREADS, smem_bytes>>>(ei, W1, b1, b2, W3, b3, out, E, n_nodes, ntiles);
}